// round 4
// baseline (speedup 1.0000x reference)
#include <cuda_runtime.h>
#include <cuda_bf16.h>
#include <cstdint>

#define T_TOK   8192
#define H_DIM   2048
#define I_DIM   4096
#define NE      8
#define LISTCAP 16384
#define TM      128
#define TN      128
#define KS      16
#define MAXTILES 144
#define HM_ROWS  17536

#define STB     16384          /* bytes per pipeline stage (Ah+Al+Bh+Bl) */
#define OFF_AL  4096
#define OFF_BH  8192
#define OFF_BL  12288

// ---------------- device scratch (no allocations allowed) ----------------
__device__ int   g_cnt[NE];
__device__ int   g_cur[NE];
__device__ int   g_base[NE];
__device__ int   g_ntiles;
__device__ int   g_tile_e[MAXTILES];
__device__ int   g_tile_m[MAXTILES];
__device__ int   g_tok[NE * LISTCAP];
__device__ float g_coef[NE * LISTCAP];

__device__ __nv_bfloat16 g_xh[(size_t)T_TOK * H_DIM];
__device__ __nv_bfloat16 g_xl[(size_t)T_TOK * H_DIM];
__device__ __nv_bfloat16 g_w13h[(size_t)NE * 2 * I_DIM * H_DIM];
__device__ __nv_bfloat16 g_w13l[(size_t)NE * 2 * I_DIM * H_DIM];
__device__ __nv_bfloat16 g_w2h[(size_t)NE * H_DIM * I_DIM];
__device__ __nv_bfloat16 g_w2l[(size_t)NE * H_DIM * I_DIM];
__device__ __nv_bfloat16 g_hmh[(size_t)HM_ROWS * I_DIM];
__device__ __nv_bfloat16 g_hml[(size_t)HM_ROWS * I_DIM];

// ---------------- helpers ----------------
__device__ __forceinline__ uint32_t smem_u32(const void* p) {
    uint32_t a;
    asm("{ .reg .u64 t; cvta.to.shared.u64 t, %1; cvt.u32.u64 %0, t; }" : "=r"(a) : "l"(p));
    return a;
}

// swizzled offset inside a [128 rows x 16 bf16] tile (32B rows, 2x16B chunks)
#define SWZ16(r, c) ((uint32_t)((r) * 32 + (((c) ^ (((r) >> 2) & 1)) << 4)))

#define CP16(dst, src) \
    asm volatile("cp.async.cg.shared.global [%0], [%1], 16;" :: "r"(dst), "l"(src))
#define CP_COMMIT() asm volatile("cp.async.commit_group;" ::: "memory")
#define CP_WAIT1()  asm volatile("cp.async.wait_group 1;" ::: "memory")
#define CP_WAIT0()  asm volatile("cp.async.wait_group 0;" ::: "memory")

__device__ __forceinline__ void ldsm4(uint32_t* r, uint32_t addr) {
    asm volatile("ldmatrix.sync.aligned.m8n8.x4.shared.b16 {%0,%1,%2,%3}, [%4];"
                 : "=r"(r[0]), "=r"(r[1]), "=r"(r[2]), "=r"(r[3]) : "r"(addr));
}

__device__ __forceinline__ void mma_bf16(float* c, const uint32_t* a,
                                         uint32_t b0, uint32_t b1) {
    asm volatile(
        "mma.sync.aligned.m16n8k16.row.col.f32.bf16.bf16.f32 "
        "{%0,%1,%2,%3}, {%4,%5,%6,%7}, {%8,%9}, {%0,%1,%2,%3};\n"
        : "+f"(c[0]), "+f"(c[1]), "+f"(c[2]), "+f"(c[3])
        : "r"(a[0]), "r"(a[1]), "r"(a[2]), "r"(a[3]), "r"(b0), "r"(b1));
}

__device__ __forceinline__ void split_f2(float a, float b, uint32_t& hi, uint32_t& lo) {
    __nv_bfloat162 h;
    h.x = __float2bfloat16(a);
    h.y = __float2bfloat16(b);
    __nv_bfloat162 l;
    l.x = __float2bfloat16(a - __bfloat162float(h.x));
    l.y = __float2bfloat16(b - __bfloat162float(h.y));
    hi = *reinterpret_cast<uint32_t*>(&h);
    lo = *reinterpret_cast<uint32_t*>(&l);
}

// ---------------- routing / prep kernels ----------------
__global__ void k_clear(float* __restrict__ out, int n) {
    int i = blockIdx.x * 256 + threadIdx.x;
    if (i < n) out[i] = 0.0f;
    if (blockIdx.x == 0 && threadIdx.x < NE) {
        g_cnt[threadIdx.x] = 0;
        g_cur[threadIdx.x] = 0;
    }
}

__global__ void k_count(const int* __restrict__ rt) {
    int t = blockIdx.x * 256 + threadIdx.x;
    if (t >= T_TOK) return;
    atomicAdd(&g_cnt[rt[t * 2 + 0]], 1);
    atomicAdd(&g_cnt[rt[t * 2 + 1]], 1);
}

__global__ void k_scan() {
    if (threadIdx.x == 0 && blockIdx.x == 0) {
        int base = 0, nt = 0;
        for (int e = 0; e < NE; ++e) {
            g_base[e] = base;
            int c = g_cnt[e];
            for (int m0 = 0; m0 < c; m0 += TM) {
                g_tile_e[nt] = e;
                g_tile_m[nt] = m0;
                nt++;
            }
            base += ((c + TM - 1) / TM) * TM;
        }
        g_ntiles = nt;
    }
}

__global__ void k_fill(const int* __restrict__ rt, const float* __restrict__ rw) {
    int t = blockIdx.x * 256 + threadIdx.x;
    if (t >= T_TOK) return;
#pragma unroll
    for (int k = 0; k < 2; ++k) {
        int e = rt[t * 2 + k];
        int p = atomicAdd(&g_cur[e], 1);
        g_tok[e * LISTCAP + p]  = t;
        g_coef[e * LISTCAP + p] = rw[t * 2 + k];
    }
}

__global__ void k_splitx(const float* __restrict__ x) {
    size_t qi = (size_t)blockIdx.x * 256 + threadIdx.x;   // over T*H/4
    int row = (int)(qi >> 9);
    int c4  = (int)(qi & 511);
    float4 v = *(const float4*)(x + (size_t)row * H_DIM + c4 * 4);
    uint32_t h0, l0, h1, l1;
    split_f2(v.x, v.y, h0, l0);
    split_f2(v.z, v.w, h1, l1);
    size_t o = (size_t)row * H_DIM + c4 * 4;
    *reinterpret_cast<uint2*>(g_xh + o) = make_uint2(h0, h1);
    *reinterpret_cast<uint2*>(g_xl + o) = make_uint2(l0, l1);
}

// split + permute w13: dst row n (of 8192 per expert) = gate j (n even) / up j (n odd)
__global__ void k_splitw13(const float* __restrict__ w13) {
    size_t qi = (size_t)blockIdx.x * 256 + threadIdx.x;   // over 8*8192*512
    int row = (int)(qi >> 9);
    int c4  = (int)(qi & 511);
    int e = row >> 13, n = row & 8191;
    int j = n >> 1;
    int src = (n & 1) ? (I_DIM + j) : j;
    float4 v = *(const float4*)(w13 + ((size_t)e * 2 * I_DIM + src) * H_DIM + c4 * 4);
    uint32_t h0, l0, h1, l1;
    split_f2(v.x, v.y, h0, l0);
    split_f2(v.z, v.w, h1, l1);
    size_t o = (size_t)row * H_DIM + c4 * 4;
    *reinterpret_cast<uint2*>(g_w13h + o) = make_uint2(h0, h1);
    *reinterpret_cast<uint2*>(g_w13l + o) = make_uint2(l0, l1);
}

__global__ void k_splitw2(const float* __restrict__ w2) {
    size_t qi = (size_t)blockIdx.x * 256 + threadIdx.x;   // over 8*2048*1024
    int row = (int)(qi >> 10);
    int c4  = (int)(qi & 1023);
    float4 v = *(const float4*)(w2 + (size_t)row * I_DIM + c4 * 4);
    uint32_t h0, l0, h1, l1;
    split_f2(v.x, v.y, h0, l0);
    split_f2(v.z, v.w, h1, l1);
    size_t o = (size_t)row * I_DIM + c4 * 4;
    *reinterpret_cast<uint2*>(g_w2h + o) = make_uint2(h0, h1);
    *reinterpret_cast<uint2*>(g_w2l + o) = make_uint2(l0, l1);
}

// ---------------- fragment compute core (one K=16 stage) ----------------
__device__ __forceinline__ void compute_stage(uint32_t st, int warp_m, int warp_n,
                                              int lane, float acc[4][4][4]) {
    const int rsel = lane & 15;
    const int csel = lane >> 4;
    uint32_t ah[4][4], al[4][4], bh2[2][4], bl2[2][4];
#pragma unroll
    for (int mf = 0; mf < 4; ++mf) {
        uint32_t a = st + SWZ16(warp_m * 64 + mf * 16 + rsel, csel);
        ldsm4(ah[mf], a);
        ldsm4(al[mf], a + OFF_AL);
    }
#pragma unroll
    for (int p = 0; p < 2; ++p) {
        uint32_t b = st + OFF_BH + SWZ16(warp_n * 32 + p * 16 + rsel, csel);
        ldsm4(bh2[p], b);
        ldsm4(bl2[p], b + (OFF_BL - OFF_BH));
    }
#pragma unroll
    for (int mf = 0; mf < 4; ++mf)
#pragma unroll
        for (int p = 0; p < 2; ++p)
#pragma unroll
            for (int s = 0; s < 2; ++s) {
                int nf = p * 2 + s;
                mma_bf16(acc[mf][nf], ah[mf], bh2[p][s], bh2[p][s + 2]);
                mma_bf16(acc[mf][nf], ah[mf], bl2[p][s], bl2[p][s + 2]);
                mma_bf16(acc[mf][nf], al[mf], bh2[p][s], bh2[p][s + 2]);
            }
}

// ---------------- GEMM1: X[gathered] @ W13p^T, SwiGLU -> Hm (split bf16) ---------
__global__ __launch_bounds__(256, 1) void k_gemm1() {
    __shared__ __align__(1024) char smem[3 * STB];

    const int tid = threadIdx.x, lane = tid & 31, wid = tid >> 5;
    const int warp_m = wid & 1, warp_n = wid >> 1;

    const int tile = blockIdx.y;
    if (tile >= g_ntiles) return;
    const int e   = g_tile_e[tile];
    const int m0  = g_tile_m[tile];
    const int n0  = blockIdx.x * TN;           // over 8192 permuted rows
    const int cnt = g_cnt[e];
    const int* tokp = g_tok + e * LISTCAP;

    // cp.async geometry: thread -> one row (r) and one 16B chunk (c) per tile
    const int r = tid >> 1, c = tid & 1;
    int m = m0 + r;
    int tok = (m < cnt) ? tokp[m] : tokp[0];
    const __nv_bfloat16* sAh = g_xh + (size_t)tok * H_DIM + c * 8;
    const __nv_bfloat16* sAl = g_xl + (size_t)tok * H_DIM + c * 8;
    const size_t brow = ((size_t)e * 2 * I_DIM + n0 + r) * H_DIM + c * 8;
    const __nv_bfloat16* sBh = g_w13h + brow;
    const __nv_bfloat16* sBl = g_w13l + brow;

    const uint32_t sb = smem_u32(smem);
    const uint32_t dA = SWZ16(r, c);

#define G1_ISSUE(it)                                                         \
    do {                                                                     \
        uint32_t b_ = sb + ((it) % 3) * STB;                                 \
        int k_ = (it) * KS;                                                  \
        CP16(b_ + dA, sAh + k_);                                             \
        CP16(b_ + OFF_AL + dA, sAl + k_);                                    \
        CP16(b_ + OFF_BH + dA, sBh + k_);                                    \
        CP16(b_ + OFF_BL + dA, sBl + k_);                                    \
        CP_COMMIT();                                                         \
    } while (0)

    float acc[4][4][4];
#pragma unroll
    for (int a = 0; a < 4; ++a)
#pragma unroll
        for (int b = 0; b < 4; ++b)
#pragma unroll
            for (int d = 0; d < 4; ++d) acc[a][b][d] = 0.0f;

    const int KT = H_DIM / KS;   // 128
    G1_ISSUE(0);
    G1_ISSUE(1);
#pragma unroll 1
    for (int it = 0; it < KT; ++it) {
        if (it < KT - 1) CP_WAIT1(); else CP_WAIT0();
        __syncthreads();
        if (it + 2 < KT) G1_ISSUE(it + 2);
        compute_stage(sb + (it % 3) * STB, warp_m, warp_n, lane, acc);
    }

    // epilogue: SwiGLU, write split bf16 Hm
    const int gq = lane >> 2, t4 = lane & 3;
    const int rowbase = g_base[e] + m0;
#pragma unroll
    for (int mf = 0; mf < 4; ++mf) {
        int rl = warp_m * 64 + mf * 16 + gq;
#pragma unroll
        for (int nf = 0; nf < 4; ++nf) {
            int j = (n0 >> 1) + warp_n * 16 + nf * 4 + t4;
#pragma unroll
            for (int h2 = 0; h2 < 2; ++h2) {
                float g = acc[mf][nf][h2 * 2];
                float u = acc[mf][nf][h2 * 2 + 1];
                float hval = u * g / (1.0f + __expf(-g));
                __nv_bfloat16 hi = __float2bfloat16(hval);
                __nv_bfloat16 lo = __float2bfloat16(hval - __bfloat162float(hi));
                size_t ro = (size_t)(rowbase + rl + h2 * 8) * I_DIM + j;
                g_hmh[ro] = hi;
                g_hml[ro] = lo;
            }
        }
    }
#undef G1_ISSUE
}

// ---------------- GEMM2: Hm @ W2^T, coef-scaled atomic scatter -> out ----------
__global__ __launch_bounds__(256, 1) void k_gemm2(float* __restrict__ out) {
    __shared__ __align__(1024) char smem[3 * STB];

    const int tid = threadIdx.x, lane = tid & 31, wid = tid >> 5;
    const int warp_m = wid & 1, warp_n = wid >> 1;

    const int tile = blockIdx.y;
    if (tile >= g_ntiles) return;
    const int e   = g_tile_e[tile];
    const int m0  = g_tile_m[tile];
    const int n0  = blockIdx.x * TN;           // over H_DIM
    const int cnt = g_cnt[e];
    const int rb  = g_base[e];

    const int r = tid >> 1, c = tid & 1;
    const size_t arow = (size_t)(rb + m0 + r) * I_DIM + c * 8;
    const __nv_bfloat16* sAh = g_hmh + arow;
    const __nv_bfloat16* sAl = g_hml + arow;
    const size_t brow = ((size_t)e * H_DIM + n0 + r) * I_DIM + c * 8;
    const __nv_bfloat16* sBh = g_w2h + brow;
    const __nv_bfloat16* sBl = g_w2l + brow;

    const uint32_t sb = smem_u32(smem);
    const uint32_t dA = SWZ16(r, c);

#define G2_ISSUE(it)                                                         \
    do {                                                                     \
        uint32_t b_ = sb + ((it) % 3) * STB;                                 \
        int k_ = (it) * KS;                                                  \
        CP16(b_ + dA, sAh + k_);                                             \
        CP16(b_ + OFF_AL + dA, sAl + k_);                                    \
        CP16(b_ + OFF_BH + dA, sBh + k_);                                    \
        CP16(b_ + OFF_BL + dA, sBl + k_);                                    \
        CP_COMMIT();                                                         \
    } while (0)

    float acc[4][4][4];
#pragma unroll
    for (int a = 0; a < 4; ++a)
#pragma unroll
        for (int b = 0; b < 4; ++b)
#pragma unroll
            for (int d = 0; d < 4; ++d) acc[a][b][d] = 0.0f;

    const int KT = I_DIM / KS;   // 256
    G2_ISSUE(0);
    G2_ISSUE(1);
#pragma unroll 1
    for (int it = 0; it < KT; ++it) {
        if (it < KT - 1) CP_WAIT1(); else CP_WAIT0();
        __syncthreads();
        if (it + 2 < KT) G2_ISSUE(it + 2);
        compute_stage(sb + (it % 3) * STB, warp_m, warp_n, lane, acc);
    }

    // epilogue: coef-scaled atomic scatter (2 commutative fp32 adds/element)
    const int gq = lane >> 2, t4 = lane & 3;
    const int* tokp = g_tok + e * LISTCAP;
    const float* cfp = g_coef + e * LISTCAP;
#pragma unroll
    for (int mf = 0; mf < 4; ++mf) {
        int ml = m0 + warp_m * 64 + mf * 16 + gq;
#pragma unroll
        for (int h2 = 0; h2 < 2; ++h2) {
            int mm = ml + h2 * 8;
            if (mm < cnt) {
                int tok  = tokp[mm];
                float cf = cfp[mm];
                float* orow = out + (size_t)tok * H_DIM;
#pragma unroll
                for (int nf = 0; nf < 4; ++nf) {
                    int col = n0 + warp_n * 32 + nf * 8 + t4 * 2;
                    atomicAdd(&orow[col],     cf * acc[mf][nf][h2 * 2]);
                    atomicAdd(&orow[col + 1], cf * acc[mf][nf][h2 * 2 + 1]);
                }
            }
        }
    }
#undef G2_ISSUE
}

// --------------------------------------------------------------------------
extern "C" void kernel_launch(void* const* d_in, const int* in_sizes, int n_in,
                              void* d_out, int out_size) {
    const float* x   = (const float*)d_in[0];
    const int*   rt  = (const int*)d_in[1];
    const float* rw  = (const float*)d_in[2];
    const float* w13 = (const float*)d_in[3];
    const float* w2  = (const float*)d_in[4];
    float* out = (float*)d_out;

    const int n = T_TOK * H_DIM;
    k_clear<<<(n + 255) / 256, 256>>>(out, n);
    k_count<<<(T_TOK + 255) / 256, 256>>>(rt);
    k_scan<<<1, 32>>>();
    k_fill<<<(T_TOK + 255) / 256, 256>>>(rt, rw);
    k_splitx<<<(int)(((size_t)T_TOK * H_DIM / 4 + 255) / 256), 256>>>(x);
    k_splitw13<<<(int)(((size_t)NE * 2 * I_DIM * H_DIM / 4 + 255) / 256), 256>>>(w13);
    k_splitw2<<<(int)(((size_t)NE * H_DIM * I_DIM / 4 + 255) / 256), 256>>>(w2);
    k_gemm1<<<dim3((2 * I_DIM) / TN, 136), 256>>>();
    k_gemm2<<<dim3(H_DIM / TN, 136), 256>>>(out);
}